// round 1
// baseline (speedup 1.0000x reference)
#include <cuda_runtime.h>
#include <stdint.h>

// Problem constants
#define BB 32      // batch
#define C  256     // channels in
#define H  56      // input spatial
#define OH 28      // output spatial
#define EPSV 1e-5f

// ---------------- scratch (device globals; no allocation) ----------------
__device__ uint32_t g_xbits[BB*H*H*8];        // [b][h][w][word]  sign(x) bits
__device__ uint32_t g_w3bits[C*9*8];          // [co][tap][word]
__device__ uint32_t g_w1bits[2*C*8];          // [co][word]
__device__ float    g_pool[(size_t)BB*OH*OH*C]; // [b][i][j][c]  avgpool(x), channel-last
__device__ float    g_h[(size_t)BB*OH*OH*C];    // [b][i][j][c]  h, channel-last
__device__ uint32_t g_hbits[BB*OH*OH*8];      // [b][i][j][word] sign(h) bits

// ---------------- weight packing ----------------
__global__ void pack_w3(const float* __restrict__ w3) {
    int tid = blockIdx.x*256 + threadIdx.x;
    if (tid >= C*9*8) return;
    int co = tid / 72;
    int r  = tid % 72;
    int tap = r >> 3, word = r & 7;
    int kh = tap / 3, kw = tap - kh*3;
    const float* p = w3 + (((size_t)co*C + word*32)*3 + kh)*3 + kw;
    uint32_t bits = 0;
    #pragma unroll
    for (int j = 0; j < 32; j++)
        if (p[(size_t)j*9] > 0.f) bits |= (1u << j);
    g_w3bits[tid] = bits;   // layout co*72 + tap*8 + word == tid
}

__global__ void pack_w1(const float* __restrict__ w1) {
    int tid = blockIdx.x*256 + threadIdx.x;
    if (tid >= 2*C*8) return;
    int co = tid >> 3, word = tid & 7;
    const float* p = w1 + (size_t)co*C + word*32;
    uint32_t bits = 0;
    #pragma unroll
    for (int j = 0; j < 32; j++)
        if (p[j] > 0.f) bits |= (1u << j);
    g_w1bits[tid] = bits;
}

// ---------------- fused pack(sign(x)) + avgpool2x2 ----------------
// grid (4 col-tiles, 28 pooled rows, 32 batch), 256 threads.
// Warp layout: 28 active lanes = 2 rows x 14 cols; warp `wid` owns channels
// [wid*32, wid*32+32) -> each lane builds word `wid` of its pixel's bitmask.
__global__ void __launch_bounds__(256) packx_pool(const float* __restrict__ x) {
    int tile = blockIdx.x;          // 0..3 : cols [tile*14, tile*14+14)
    int i    = blockIdx.y;          // pooled row 0..27
    int b    = blockIdx.z;
    int tid = threadIdx.x, wid = tid >> 5, lane = tid & 31;

    __shared__ float s_pool[7*256];                 // [j_local][c]
    __shared__ __align__(16) uint32_t s_bits[28*8]; // [pixel][word]

    int r = lane / 14;              // 0 or 1 (garbage for lanes>=28)
    int q = lane - r*14;
    bool active = (lane < 28);
    int rr = active ? r : 0;        // clamp so OOB lanes form a safe address
    int row = 2*i + rr;
    int col = tile*14 + q;

    const float* xp = x + (((size_t)b*C + wid*32)*H + row)*H + col;

    uint32_t word = 0;
    #pragma unroll
    for (int k = 0; k < 32; k++) {
        float v = active ? xp[(size_t)k*H*H] : 0.f;
        if (v > 0.f) word |= (1u << k);
        // 2x2 pooling: combine rows (lane, lane+14), then col pairs (q, q+1)
        float rs = v  + __shfl_down_sync(0xffffffffu, v, 14);
        float ps = rs + __shfl_down_sync(0xffffffffu, rs, 1);
        if (lane < 14 && (lane & 1) == 0)
            s_pool[(lane >> 1)*256 + wid*32 + k] = ps * 0.25f;
    }
    if (active) s_bits[lane*8 + wid] = word;
    __syncthreads();

    // write xbits (two contiguous 448B row segments)
    for (int idx = tid; idx < 28*8; idx += 256) {
        int p  = idx >> 3, w = idx & 7;
        int pr = p / 14, pq = p - pr*14;
        g_xbits[ (((size_t)b*H + 2*i + pr)*H + tile*14 + pq)*8 + w ] = s_bits[idx];
    }
    // write pool (channel-last), 7 coalesced 1KB chunks
    for (int idx = tid; idx < 7*256; idx += 256) {
        int jl = idx >> 8, c = idx & 255;
        g_pool[ (((size_t)b*OH + i)*OH + tile*7 + jl)*C + c ] = s_pool[idx];
    }
}

// ---------------- binary 3x3 stride-2 conv + BN + pool shortcut + sign ----------------
// grid (28 rows, 32 batch), 256 threads = one thread per output channel.
__global__ void __launch_bounds__(256) conv3(
    const float* __restrict__ g3, const float* __restrict__ b3,
    const float* __restrict__ m3, const float* __restrict__ v3)
{
    int ho = blockIdx.x, b = blockIdx.y;
    int tid = threadIdx.x, wid = tid >> 5, lane = tid & 31;
    int co = tid;

    __shared__ __align__(16) uint32_t s_x[3*H*8];   // [kh][col][word]

    // per-thread weights: 9 taps x 8 words = 72 regs
    uint32_t wreg[72];
    {
        const uint4* wp = (const uint4*)(g_w3bits + (size_t)co*72);
        #pragma unroll
        for (int t = 0; t < 18; t++) {
            uint4 u = wp[t];
            wreg[t*4+0] = u.x; wreg[t*4+1] = u.y;
            wreg[t*4+2] = u.z; wreg[t*4+3] = u.w;
        }
    }

    // x-bit tile: input rows 2*ho-1 .. 2*ho+1 (top row absent for ho==0)
    int r0 = 2*ho - 1;
    for (int idx = tid; idx < 3*H*8; idx += 256) {
        int kh  = idx / (H*8);
        int rem = idx - kh*(H*8);
        int row = r0 + kh;
        s_x[idx] = (row >= 0) ? g_xbits[ ((size_t)(b*H + row)*H)*8 + rem ] : 0u;
    }
    __syncthreads();

    float inv = g3[co] * rsqrtf(v3[co] + EPSV);
    float add = b3[co] - m3[co]*inv;
    int skip_top = (ho == 0);

    for (int wo = 0; wo < OH; wo++) {
        int cb = 2*wo - 1;
        int P = 0;
        #pragma unroll
        for (int kh = 0; kh < 3; kh++) {
            if (kh == 0 && skip_top) continue;          // uniform branch
            #pragma unroll
            for (int kw = 0; kw < 3; kw++) {
                int ccol = cb + kw;
                if (ccol < 0) continue;                 // only wo==0,kw==0
                const uint4* xp = (const uint4*)(s_x + (kh*H + ccol)*8);
                uint4 a  = xp[0];
                uint4 c4 = xp[1];
                const int wb = (kh*3 + kw)*8;
                P += __popc(a.x  ^ wreg[wb+0]);
                P += __popc(a.y  ^ wreg[wb+1]);
                P += __popc(a.z  ^ wreg[wb+2]);
                P += __popc(a.w  ^ wreg[wb+3]);
                P += __popc(c4.x ^ wreg[wb+4]);
                P += __popc(c4.y ^ wreg[wb+5]);
                P += __popc(c4.z ^ wreg[wb+6]);
                P += __popc(c4.w ^ wreg[wb+7]);
            }
        }
        int nval = ((ho == 0) ? 2 : 3) * ((wo == 0) ? 2 : 3);
        float dot = (float)(C*nval - 2*P);
        size_t pix = ((size_t)(b*OH + ho))*OH + wo;
        float hv = dot*inv + add + g_pool[pix*C + co];
        g_h[pix*C + co] = hv;
        unsigned mask = __ballot_sync(0xffffffffu, hv > 0.f);
        if (lane == 0) g_hbits[pix*8 + wid] = mask;
    }
}

// ---------------- binary 1x1 conv (512 out) + BN + concat(h,h) shortcut ----------------
// grid (28 rows, 32 batch), 256 threads; thread t handles co = t and t+256.
__global__ void __launch_bounds__(256) conv1(
    const float* __restrict__ g1, const float* __restrict__ b1,
    const float* __restrict__ m1, const float* __restrict__ v1,
    float* __restrict__ out)
{
    int ho = blockIdx.x, b = blockIdx.y;
    int tid = threadIdx.x;
    int co = tid;

    __shared__ __align__(16) uint32_t s_hb[OH*8];
    __shared__ __align__(16) float    s_h[OH*256];   // 28 KB

    size_t pix0 = ((size_t)(b*OH + ho))*OH;
    if (tid < OH*8) s_hb[tid] = g_hbits[pix0*8 + tid];
    {
        const float4* src = (const float4*)(g_h + pix0*C);
        float4* dst = (float4*)s_h;
        for (int t = tid; t < OH*256/4; t += 256) dst[t] = src[t];
    }

    uint32_t wa[8], wb[8];
    {
        const uint4* p0 = (const uint4*)(g_w1bits + (size_t)co*8);
        uint4 u0 = p0[0], u1 = p0[1];
        wa[0]=u0.x; wa[1]=u0.y; wa[2]=u0.z; wa[3]=u0.w;
        wa[4]=u1.x; wa[5]=u1.y; wa[6]=u1.z; wa[7]=u1.w;
        const uint4* p1 = (const uint4*)(g_w1bits + (size_t)(co+256)*8);
        uint4 v0 = p1[0], v1u = p1[1];
        wb[0]=v0.x; wb[1]=v0.y; wb[2]=v0.z; wb[3]=v0.w;
        wb[4]=v1u.x; wb[5]=v1u.y; wb[6]=v1u.z; wb[7]=v1u.w;
    }
    float invA = g1[co]     * rsqrtf(v1[co]     + EPSV);
    float addA = b1[co]     - m1[co]    *invA;
    float invB = g1[co+256] * rsqrtf(v1[co+256] + EPSV);
    float addB = b1[co+256] - m1[co+256]*invB;
    __syncthreads();

    for (int wo = 0; wo < OH; wo++) {
        const uint4* hp = (const uint4*)(s_hb + wo*8);
        uint4 h0 = hp[0], h1 = hp[1];
        int P0 = 0, P1 = 0;
        P0 += __popc(h0.x ^ wa[0]); P0 += __popc(h0.y ^ wa[1]);
        P0 += __popc(h0.z ^ wa[2]); P0 += __popc(h0.w ^ wa[3]);
        P0 += __popc(h1.x ^ wa[4]); P0 += __popc(h1.y ^ wa[5]);
        P0 += __popc(h1.z ^ wa[6]); P0 += __popc(h1.w ^ wa[7]);
        P1 += __popc(h0.x ^ wb[0]); P1 += __popc(h0.y ^ wb[1]);
        P1 += __popc(h0.z ^ wb[2]); P1 += __popc(h0.w ^ wb[3]);
        P1 += __popc(h1.x ^ wb[4]); P1 += __popc(h1.y ^ wb[5]);
        P1 += __popc(h1.z ^ wb[6]); P1 += __popc(h1.w ^ wb[7]);
        float hv = s_h[wo*256 + co];
        float oA = (float)(C - 2*P0)*invA + addA + hv;
        float oB = (float)(C - 2*P1)*invB + addB + hv;
        out[(((size_t)b*512 + co      )*OH + ho)*OH + wo] = oA;
        out[(((size_t)b*512 + co + 256)*OH + ho)*OH + wo] = oB;
    }
}

// ---------------- launch ----------------
extern "C" void kernel_launch(void* const* d_in, const int* in_sizes, int n_in,
                              void* d_out, int out_size) {
    const float* x  = (const float*)d_in[0];
    const float* w3 = (const float*)d_in[1];
    const float* g3 = (const float*)d_in[2];
    const float* b3 = (const float*)d_in[3];
    const float* m3 = (const float*)d_in[4];
    const float* v3 = (const float*)d_in[5];
    const float* w1 = (const float*)d_in[6];
    const float* g1 = (const float*)d_in[7];
    const float* b1 = (const float*)d_in[8];
    const float* m1 = (const float*)d_in[9];
    const float* v1 = (const float*)d_in[10];
    float* out = (float*)d_out;

    pack_w3<<<(C*9*8 + 255)/256, 256>>>(w3);
    pack_w1<<<(2*C*8 + 255)/256, 256>>>(w1);
    packx_pool<<<dim3(4, OH, BB), 256>>>(x);
    conv3<<<dim3(OH, BB), 256>>>(g3, b3, m3, v3);
    conv1<<<dim3(OH, BB), 256>>>(g1, b1, m1, v1, out);
}

// round 4
// speedup vs baseline: 1.3554x; 1.3554x over previous
#include <cuda_runtime.h>
#include <stdint.h>

#define BB 32
#define C  256
#define H  56
#define OH 28
#define EPSV 1e-5f

// ---------------- scratch ----------------
__device__ uint32_t g_xbits[BB*H*H*8];          // [b][h][w][word]
__device__ uint32_t g_w3bits[C*9*8];            // [co][tap][word]
__device__ uint32_t g_w1bits[2*C*8];            // [co][word]
__device__ float    g_pool[(size_t)BB*OH*OH*C]; // [b][i][j][c]
__device__ float    g_h[(size_t)BB*OH*OH*C];    // [b][i][j][c]

// ---------------- weight packing ----------------
__global__ void pack_w3(const float* __restrict__ w3) {
    int tid = blockIdx.x*256 + threadIdx.x;
    if (tid >= C*9*8) return;
    int co = tid / 72;
    int r  = tid % 72;
    int tap = r >> 3, word = r & 7;
    int kh = tap / 3, kw = tap - kh*3;
    const float* p = w3 + (((size_t)co*C + word*32)*3 + kh)*3 + kw;
    uint32_t bits = 0;
    #pragma unroll
    for (int j = 0; j < 32; j++)
        if (p[(size_t)j*9] > 0.f) bits |= (1u << j);
    g_w3bits[tid] = bits;
}

__global__ void pack_w1(const float* __restrict__ w1) {
    int tid = blockIdx.x*256 + threadIdx.x;
    if (tid >= 2*C*8) return;
    int co = tid >> 3, word = tid & 7;
    const float* p = w1 + (size_t)co*C + word*32;
    uint32_t bits = 0;
    #pragma unroll
    for (int j = 0; j < 32; j++)
        if (p[j] > 0.f) bits |= (1u << j);
    g_w1bits[tid] = bits;
}

// ---------------- fused pack(sign(x)) + avgpool2x2 ----------------
__global__ void __launch_bounds__(256) packx_pool(const float* __restrict__ x) {
    int tile = blockIdx.x;
    int i    = blockIdx.y;
    int b    = blockIdx.z;
    int tid = threadIdx.x, wid = tid >> 5, lane = tid & 31;

    __shared__ float s_pool[7*256];
    __shared__ __align__(16) uint32_t s_bits[28*8];

    int r = lane / 14;
    int q = lane - r*14;
    bool active = (lane < 28);
    int rr = active ? r : 0;
    int row = 2*i + rr;
    int col = tile*14 + q;

    const float* xp = x + (((size_t)b*C + wid*32)*H + row)*H + col;

    uint32_t word = 0;
    #pragma unroll
    for (int k = 0; k < 32; k++) {
        float v = active ? xp[(size_t)k*H*H] : 0.f;
        if (v > 0.f) word |= (1u << k);
        float rs = v  + __shfl_down_sync(0xffffffffu, v, 14);
        float ps = rs + __shfl_down_sync(0xffffffffu, rs, 1);
        if (lane < 14 && (lane & 1) == 0)
            s_pool[(lane >> 1)*256 + wid*32 + k] = ps * 0.25f;
    }
    if (active) s_bits[lane*8 + wid] = word;
    __syncthreads();

    for (int idx = tid; idx < 28*8; idx += 256) {
        int p  = idx >> 3, w = idx & 7;
        int pr = p / 14, pq = p - pr*14;
        g_xbits[ (((size_t)b*H + 2*i + pr)*H + tile*14 + pq)*8 + w ] = s_bits[idx];
    }
    for (int idx = tid; idx < 7*256; idx += 256) {
        int jl = idx >> 8, c = idx & 255;
        g_pool[ (((size_t)b*OH + i)*OH + tile*7 + jl)*C + c ] = s_pool[idx];
    }
}

// ---------------- binary 3x3 s2 conv + BN + pool shortcut ----------------
// 512 threads: thread t -> co = t>>1, half = t&1 (4 bit-words each).
// s_x is left-padded with a zero column; border handling via popcount
// corrections, so the inner loop is fully branch-free.
__global__ void __launch_bounds__(512, 2) conv3(
    const float* __restrict__ g3, const float* __restrict__ b3,
    const float* __restrict__ m3, const float* __restrict__ v3)
{
    int ho = blockIdx.x, b = blockIdx.y;
    int tid = threadIdx.x;
    int co   = tid >> 1;
    int half = tid & 1;

    __shared__ __align__(16) uint32_t s_x[3*57*8];   // [kh][1+col][word]

    // weights: 9 taps x 4 words (this thread's half)
    uint4 wq[9];
    {
        const uint4* wp = (const uint4*)(g_w3bits + (size_t)co*72 + half*4);
        #pragma unroll
        for (int t = 0; t < 9; t++) wq[t] = wp[t*2];
    }

    // load padded x-bit tile: rows 2*ho-1 .. 2*ho+1
    int r0 = 2*ho - 1;
    for (int idx = tid; idx < 3*57*8; idx += 512) {
        int kh  = idx / 456;
        int rem = idx - kh*456;
        int col = rem >> 3;
        int w   = rem & 7;
        int row = r0 + kh;
        uint32_t v = 0u;
        if (col > 0 && row >= 0)
            v = g_xbits[ (((size_t)b*H + row)*H + (col-1))*8 + w ];
        s_x[idx] = v;
    }

    // popcount corrections (half-contributions, combined via shfl)
    int topc = 0, leftc = 0, tlc = 0;
    #pragma unroll
    for (int kw = 0; kw < 3; kw++)
        topc += __popc(wq[kw].x)+__popc(wq[kw].y)+__popc(wq[kw].z)+__popc(wq[kw].w);
    #pragma unroll
    for (int kh = 0; kh < 3; kh++)
        leftc += __popc(wq[kh*3].x)+__popc(wq[kh*3].y)+__popc(wq[kh*3].z)+__popc(wq[kh*3].w);
    tlc = __popc(wq[0].x)+__popc(wq[0].y)+__popc(wq[0].z)+__popc(wq[0].w);
    topc  += __shfl_xor_sync(0xffffffffu, topc, 1);
    leftc += __shfl_xor_sync(0xffffffffu, leftc, 1);
    tlc   += __shfl_xor_sync(0xffffffffu, tlc, 1);

    float inv = g3[co] * rsqrtf(v3[co] + EPSV);
    float add = b3[co] - m3[co]*inv;

    int nrow = (ho == 0) ? 2 : 3;
    float Kmain = (float)(nrow*3*256 + ((ho == 0) ? 2*topc : 0));
    int corr0 = leftc + ((ho == 0) ? (topc - tlc) : 0);
    float K0 = (float)(nrow*2*256 + 2*corr0);

    __syncthreads();

    size_t pixbase = ((size_t)(b*OH + ho))*OH;

    for (int wo = 0; wo < OH; wo++) {
        int base = 2*wo;   // padded column index of kw=0
        int P0 = 0, P1 = 0, P2 = 0, P3 = 0;
        #pragma unroll
        for (int kh = 0; kh < 3; kh++) {
            #pragma unroll
            for (int kw = 0; kw < 3; kw++) {
                uint4 a = *(const uint4*)(s_x + (kh*57 + base + kw)*8 + half*4);
                uint4 w = wq[kh*3 + kw];
                P0 += __popc(a.x ^ w.x);
                P1 += __popc(a.y ^ w.y);
                P2 += __popc(a.z ^ w.z);
                P3 += __popc(a.w ^ w.w);
            }
        }
        int P = (P0 + P1) + (P2 + P3);
        P += __shfl_xor_sync(0xffffffffu, P, 1);
        if (half == 0) {
            float Kc = (wo == 0) ? K0 : Kmain;
            size_t pix = pixbase + wo;
            float hv = (Kc - 2.0f*(float)P)*inv + add + g_pool[pix*C + co];
            g_h[pix*C + co] = hv;
        }
    }
}

// ---------------- binary 1x1 conv + BN + concat(h,h) ----------------
// Load phase: threads=co, ballot-pack sign(h) per pixel.
// Pass phase: warp per co, lane per wo -> coalesced NCHW stores.
// 1x1 weights stay in L1/L2 (warp-uniform __ldg broadcast), keeping smem <48KB.
__global__ void __launch_bounds__(256) conv1(
    const float* __restrict__ g1, const float* __restrict__ b1,
    const float* __restrict__ m1, const float* __restrict__ v1,
    float* __restrict__ out)
{
    int ho = blockIdx.x, b = blockIdx.y;
    int tid = threadIdx.x, wid = tid >> 5, lane = tid & 31;

    __shared__ float    s_h[28*257];       // [wo][co], pad 257 vs bank conflicts
    __shared__ uint32_t s_hb[28*9];        // [wo][word], pad 9
    __shared__ float    s_inv[512], s_add[512];

    size_t pix0 = ((size_t)(b*OH + ho))*OH;

    // load h row + ballot-pack sign bits
    #pragma unroll 4
    for (int wo = 0; wo < OH; wo++) {
        float v = g_h[(pix0 + wo)*C + tid];
        s_h[wo*257 + tid] = v;
        unsigned m = __ballot_sync(0xffffffffu, v > 0.f);
        if (lane == 0) s_hb[wo*9 + wid] = m;
    }
    // BN scalars
    {
        int c0 = tid, c1 = tid + 256;
        float i0 = g1[c0]*rsqrtf(v1[c0]+EPSV);
        float i1 = g1[c1]*rsqrtf(v1[c1]+EPSV);
        s_inv[c0] = i0;  s_add[c0] = b1[c0] - m1[c0]*i0;
        s_inv[c1] = i1;  s_add[c1] = b1[c1] - m1[c1]*i1;
    }
    __syncthreads();

    // per-lane h-bits (lane = wo), loaded once
    int lw = (lane < 28) ? lane : 27;
    uint32_t hb[8];
    #pragma unroll
    for (int w = 0; w < 8; w++) hb[w] = s_hb[lw*9 + w];

    const uint4* wtab = (const uint4*)g_w1bits;
    for (int co = wid; co < 512; co += 8) {
        uint4 w0 = __ldg(wtab + co*2);
        uint4 w1q = __ldg(wtab + co*2 + 1);
        int P = 0;
        P += __popc(hb[0] ^ w0.x);  P += __popc(hb[1] ^ w0.y);
        P += __popc(hb[2] ^ w0.z);  P += __popc(hb[3] ^ w0.w);
        P += __popc(hb[4] ^ w1q.x); P += __popc(hb[5] ^ w1q.y);
        P += __popc(hb[6] ^ w1q.z); P += __popc(hb[7] ^ w1q.w);
        int hc = (co < 256) ? co : (co - 256);
        float hv = s_h[lw*257 + hc];
        float o = (float)(256 - 2*P)*s_inv[co] + s_add[co] + hv;
        if (lane < 28)
            out[(((size_t)b*512 + co)*OH + ho)*OH + lane] = o;
    }
}

// ---------------- launch ----------------
extern "C" void kernel_launch(void* const* d_in, const int* in_sizes, int n_in,
                              void* d_out, int out_size) {
    const float* x  = (const float*)d_in[0];
    const float* w3 = (const float*)d_in[1];
    const float* g3 = (const float*)d_in[2];
    const float* b3 = (const float*)d_in[3];
    const float* m3 = (const float*)d_in[4];
    const float* v3 = (const float*)d_in[5];
    const float* w1 = (const float*)d_in[6];
    const float* g1 = (const float*)d_in[7];
    const float* b1 = (const float*)d_in[8];
    const float* m1 = (const float*)d_in[9];
    const float* v1 = (const float*)d_in[10];
    float* out = (float*)d_out;

    pack_w3<<<(C*9*8 + 255)/256, 256>>>(w3);
    pack_w1<<<(2*C*8 + 255)/256, 256>>>(w1);
    packx_pool<<<dim3(4, OH, BB), 256>>>(x);
    conv3<<<dim3(OH, BB), 512>>>(g3, b3, m3, v3);
    conv1<<<dim3(OH, BB), 256>>>(g1, b1, m1, v1, out);
}

// round 6
// speedup vs baseline: 1.4539x; 1.0727x over previous
#include <cuda_runtime.h>
#include <stdint.h>

#define BB 32
#define C  256
#define H  56
#define OH 28
#define EPSV 1e-5f

// ---------------- scratch ----------------
__device__ uint32_t g_xbits[BB*H*H*8];          // [b][h][w][word]
__device__ uint32_t g_w3bits[C*9*8];            // [co][tap][word]
__device__ uint32_t g_w1bits[2*C*8];            // [co][word]
__device__ float    g_pool[(size_t)BB*OH*OH*C]; // [b][i][j][c]

// ---------------- weight packing (both convs, one launch) ----------------
__global__ void pack_w(const float* __restrict__ w3, const float* __restrict__ w1) {
    int tid = blockIdx.x*256 + threadIdx.x;
    if (tid < C*9*8) {
        int co = tid / 72;
        int r  = tid % 72;
        int tap = r >> 3, word = r & 7;
        int kh = tap / 3, kw = tap - kh*3;
        const float* p = w3 + (((size_t)co*C + word*32)*3 + kh)*3 + kw;
        uint32_t bits = 0;
        #pragma unroll
        for (int j = 0; j < 32; j++)
            if (p[(size_t)j*9] > 0.f) bits |= (1u << j);
        g_w3bits[tid] = bits;
    } else if (tid < C*9*8 + 2*C*8) {
        int t = tid - C*9*8;
        int co = t >> 3, word = t & 7;
        const float* p = w1 + (size_t)co*C + word*32;
        uint32_t bits = 0;
        #pragma unroll
        for (int j = 0; j < 32; j++)
            if (p[j] > 0.f) bits |= (1u << j);
        g_w1bits[t] = bits;
    }
}

// ---------------- fused pack(sign(x)) + avgpool2x2 ----------------
__global__ void __launch_bounds__(256) packx_pool(const float* __restrict__ x) {
    int tile = blockIdx.x;
    int i    = blockIdx.y;
    int b    = blockIdx.z;
    int tid = threadIdx.x, wid = tid >> 5, lane = tid & 31;

    __shared__ float s_pool[7*256];
    __shared__ __align__(16) uint32_t s_bits[28*8];

    int r = lane / 14;
    int q = lane - r*14;
    bool active = (lane < 28);
    int rr = active ? r : 0;
    int row = 2*i + rr;
    int col = tile*14 + q;

    const float* xp = x + (((size_t)b*C + wid*32)*H + row)*H + col;

    uint32_t word = 0;
    #pragma unroll
    for (int k = 0; k < 32; k++) {
        float v = active ? xp[(size_t)k*H*H] : 0.f;
        if (v > 0.f) word |= (1u << k);
        float rs = v  + __shfl_down_sync(0xffffffffu, v, 14);
        float ps = rs + __shfl_down_sync(0xffffffffu, rs, 1);
        if (lane < 14 && (lane & 1) == 0)
            s_pool[(lane >> 1)*256 + wid*32 + k] = ps * 0.25f;
    }
    if (active) s_bits[lane*8 + wid] = word;
    __syncthreads();

    for (int idx = tid; idx < 28*8; idx += 256) {
        int p  = idx >> 3, w = idx & 7;
        int pr = p / 14, pq = p - pr*14;
        g_xbits[ (((size_t)b*H + 2*i + pr)*H + tile*14 + pq)*8 + w ] = s_bits[idx];
    }
    for (int idx = tid; idx < 7*256; idx += 256) {
        int jl = idx >> 8, c = idx & 255;
        g_pool[ (((size_t)b*OH + i)*OH + tile*7 + jl)*C + c ] = s_pool[idx];
    }
}

// ------- fused: binary3x3+BN+pool-shortcut -> sign -> binary1x1+BN+concat -------
// Block = one (b, ho) output row, 512 threads.
// Phase A (conv3): thread t -> co=t>>1, half=t&1; hv kept in smem.
// Phase B: ballot-pack sign(h); Phase C: 1x1 pass, warp-per-co, lane-per-wo.
__global__ void __launch_bounds__(512, 2) fused_conv(
    const float* __restrict__ g3, const float* __restrict__ b3,
    const float* __restrict__ m3, const float* __restrict__ v3,
    const float* __restrict__ g1, const float* __restrict__ b1,
    const float* __restrict__ m1, const float* __restrict__ v1,
    float* __restrict__ out)
{
    int ho = blockIdx.x, b = blockIdx.y;
    int tid = threadIdx.x, wid = tid >> 5, lane = tid & 31;
    int co   = tid >> 1;
    int half = tid & 1;

    __shared__ __align__(16) uint32_t s_x[3*57*8];   // 5.3 KB
    __shared__ float    s_h[28*257];                 // 28.8 KB
    __shared__ uint32_t s_hb[28*9];                  // 1.0 KB
    __shared__ float    s_inv[512], s_add[512];      // 4 KB

    // ---- Phase A: binary 3x3 ----
    uint4 wq[9];
    {
        const uint4* wp = (const uint4*)(g_w3bits + (size_t)co*72 + half*4);
        #pragma unroll
        for (int t = 0; t < 9; t++) wq[t] = wp[t*2];
    }

    int r0 = 2*ho - 1;
    for (int idx = tid; idx < 3*57*8; idx += 512) {
        int kh  = idx / 456;
        int rem = idx - kh*456;
        int col = rem >> 3;
        int w   = rem & 7;
        int row = r0 + kh;
        uint32_t v = 0u;
        if (col > 0 && row >= 0)
            v = g_xbits[ (((size_t)b*H + row)*H + (col-1))*8 + w ];
        s_x[idx] = v;
    }

    // popcount border corrections
    int topc = 0, leftc = 0, tlc = 0;
    #pragma unroll
    for (int kw = 0; kw < 3; kw++)
        topc += __popc(wq[kw].x)+__popc(wq[kw].y)+__popc(wq[kw].z)+__popc(wq[kw].w);
    #pragma unroll
    for (int kh = 0; kh < 3; kh++)
        leftc += __popc(wq[kh*3].x)+__popc(wq[kh*3].y)+__popc(wq[kh*3].z)+__popc(wq[kh*3].w);
    tlc = __popc(wq[0].x)+__popc(wq[0].y)+__popc(wq[0].z)+__popc(wq[0].w);
    topc  += __shfl_xor_sync(0xffffffffu, topc, 1);
    leftc += __shfl_xor_sync(0xffffffffu, leftc, 1);
    tlc   += __shfl_xor_sync(0xffffffffu, tlc, 1);

    float inv = g3[co] * rsqrtf(v3[co] + EPSV);
    float add = b3[co] - m3[co]*inv;

    int nrow = (ho == 0) ? 2 : 3;
    float Kmain = (float)(nrow*3*256 + ((ho == 0) ? 2*topc : 0));
    int corr0 = leftc + ((ho == 0) ? (topc - tlc) : 0);
    float K0 = (float)(nrow*2*256 + 2*corr0);

    // BN1 scalars (independent of phase A math; do while tile settles)
    {
        float i1v = g1[tid]*rsqrtf(v1[tid]+EPSV);
        s_inv[tid] = i1v;
        s_add[tid] = b1[tid] - m1[tid]*i1v;
    }
    __syncthreads();

    size_t pixbase = ((size_t)(b*OH + ho))*OH;

    // prefetch pool[wo=0]
    float poolv = (half == 0) ? g_pool[pixbase*C + co] : 0.f;

    #pragma unroll 2
    for (int wo = 0; wo < OH; wo++) {
        int base = 2*wo;
        int P0 = 0, P1 = 0, P2 = 0, P3 = 0;
        #pragma unroll
        for (int kh = 0; kh < 3; kh++) {
            #pragma unroll
            for (int kw = 0; kw < 3; kw++) {
                uint4 a = *(const uint4*)(s_x + (kh*57 + base + kw)*8 + half*4);
                uint4 w = wq[kh*3 + kw];
                P0 += __popc(a.x ^ w.x);
                P1 += __popc(a.y ^ w.y);
                P2 += __popc(a.z ^ w.z);
                P3 += __popc(a.w ^ w.w);
            }
        }
        // prefetch next wo's pool value before the dependent tail
        float poolnext = (half == 0 && wo+1 < OH) ? g_pool[(pixbase + wo+1)*C + co] : 0.f;
        int P = (P0 + P1) + (P2 + P3);
        P += __shfl_xor_sync(0xffffffffu, P, 1);
        if (half == 0) {
            float Kc = (wo == 0) ? K0 : Kmain;
            s_h[wo*257 + co] = (Kc - 2.0f*(float)P)*inv + add + poolv;
        }
        poolv = poolnext;
    }
    __syncthreads();

    // ---- Phase B: ballot-pack sign(h) (all 16 warps; 2 wo groups) ----
    {
        int grp = tid >> 8;          // 0 or 1
        int c   = tid & 255;
        int wo0 = grp*14;
        #pragma unroll
        for (int k = 0; k < 14; k++) {
            int wo = wo0 + k;
            float v = s_h[wo*257 + c];
            unsigned m = __ballot_sync(0xffffffffu, v > 0.f);
            if (lane == 0) s_hb[wo*9 + (c >> 5)] = m;
        }
    }
    __syncthreads();

    // ---- Phase C: binary 1x1 + BN + concat shortcut ----
    int lw = (lane < 28) ? lane : 27;
    uint32_t hb[8];
    #pragma unroll
    for (int w = 0; w < 8; w++) hb[w] = s_hb[lw*9 + w];

    const uint4* wtab = (const uint4*)g_w1bits;
    for (int c1 = wid; c1 < 512; c1 += 16) {
        uint4 w0 = __ldg(wtab + c1*2);
        uint4 w1q = __ldg(wtab + c1*2 + 1);
        int P = 0;
        P += __popc(hb[0] ^ w0.x);  P += __popc(hb[1] ^ w0.y);
        P += __popc(hb[2] ^ w0.z);  P += __popc(hb[3] ^ w0.w);
        P += __popc(hb[4] ^ w1q.x); P += __popc(hb[5] ^ w1q.y);
        P += __popc(hb[6] ^ w1q.z); P += __popc(hb[7] ^ w1q.w);
        float hv = s_h[lw*257 + (c1 & 255)];
        float o = (float)(256 - 2*P)*s_inv[c1] + s_add[c1] + hv;
        if (lane < 28)
            out[(((size_t)b*512 + c1)*OH + ho)*OH + lane] = o;
    }
}

// ---------------- launch ----------------
extern "C" void kernel_launch(void* const* d_in, const int* in_sizes, int n_in,
                              void* d_out, int out_size) {
    const float* x  = (const float*)d_in[0];
    const float* w3 = (const float*)d_in[1];
    const float* g3 = (const float*)d_in[2];
    const float* b3 = (const float*)d_in[3];
    const float* m3 = (const float*)d_in[4];
    const float* v3 = (const float*)d_in[5];
    const float* w1 = (const float*)d_in[6];
    const float* g1 = (const float*)d_in[7];
    const float* b1 = (const float*)d_in[8];
    const float* m1 = (const float*)d_in[9];
    const float* v1 = (const float*)d_in[10];
    float* out = (float*)d_out;

    pack_w<<<(C*9*8 + 2*C*8 + 255)/256, 256>>>(w3, w1);
    packx_pool<<<dim3(4, OH, BB), 256>>>(x);
    fused_conv<<<dim3(OH, BB), 512>>>(g3, b3, m3, v3, g1, b1, m1, v1, out);
}

// round 8
// speedup vs baseline: 1.5090x; 1.0379x over previous
#include <cuda_runtime.h>
#include <stdint.h>

#define BB 32
#define C  256
#define H  56
#define OH 28
#define HP 58
#define EPSV 1e-5f
#define NPIX (BB*OH*OH)     // 25088
#define NBLK (NPIX/64)      // 392

// ---------------- scratch ----------------
__device__ uint32_t g_x8u[BB*HP*HP*64];       // s8 sign(x), padded, channel-last
__device__ uint32_t g_w3q[9*4*256*16];        // s8 sign(w3): [tap][chunk64][co][16 u32]
__device__ uint32_t g_w1bits[2*C*8];          // 1x1 weight sign bits
__device__ float    g_pool[(size_t)NPIX*C];   // [pix][c]

// ---------------- s8 mma (sm_80+ PTX; runs on tensor pipe) ----------------
__device__ __forceinline__ void mma_s8(int* c, const uint32_t* a, const uint32_t* b) {
    asm volatile(
        "mma.sync.aligned.m16n8k32.row.col.s32.s8.s8.s32 "
        "{%0,%1,%2,%3}, {%4,%5,%6,%7}, {%8,%9}, {%0,%1,%2,%3};"
        : "+r"(c[0]), "+r"(c[1]), "+r"(c[2]), "+r"(c[3])
        : "r"(a[0]), "r"(a[1]), "r"(a[2]), "r"(a[3]), "r"(b[0]), "r"(b[1]));
}

// ---------------- weight packing ----------------
__global__ void pack_w(const float* __restrict__ w3, const float* __restrict__ w1) {
    int t = blockIdx.x*256 + threadIdx.x;
    if (t < 9*4*256*16) {
        int tap = t / 16384;
        int r   = t - tap*16384;
        int chunk = r >> 12;
        int r2  = r & 4095;
        int co  = r2 >> 4;
        int w4  = r2 & 15;
        int kh = tap / 3, kw = tap - kh*3;
        uint32_t pk = 0;
        #pragma unroll
        for (int z = 0; z < 4; z++) {
            int ci = chunk*64 + w4*4 + z;
            float v = w3[(((size_t)co*256 + ci)*3 + kh)*3 + kw];
            int s = (v > 0.f) - (v < 0.f);
            pk |= ((uint32_t)(uint8_t)(int8_t)s) << (z*8);
        }
        g_w3q[t] = pk;
    } else if (t < 9*4*256*16 + 2*C*8) {
        int tt = t - 9*4*256*16;
        int co = tt >> 3, word = tt & 7;
        const float* p = w1 + (size_t)co*C + word*32;
        uint32_t bits = 0;
        #pragma unroll
        for (int j = 0; j < 32; j++)
            if (p[j] > 0.f) bits |= (1u << j);
        g_w1bits[tt] = bits;
    }
}

// ---------------- zero padded border of X8 ----------------
__global__ void border_zero() {
    int b = blockIdx.x, t = threadIdx.x;
    size_t base = (size_t)b*HP*HP*64;
    for (int i = t; i < HP*64; i += 256) {
        g_x8u[base + i] = 0;
        g_x8u[base + (size_t)(HP-1)*HP*64 + i] = 0;
    }
    for (int i = t; i < (HP-2)*64; i += 256) {
        int r = i >> 6, c = i & 63;
        g_x8u[base + (size_t)(r+1)*HP*64 + c] = 0;
        g_x8u[base + (size_t)(r+1)*HP*64 + (HP-1)*64 + c] = 0;
    }
}

// ---------------- fused s8-pack(sign(x)) + avgpool2x2 ----------------
__global__ void __launch_bounds__(256) packx8_pool(const float* __restrict__ x) {
    int tile = blockIdx.x;
    int i    = blockIdx.y;
    int b    = blockIdx.z;
    int tid = threadIdx.x, wid = tid >> 5, lane = tid & 31;

    __shared__ float    s_pool[7*256];
    __shared__ uint32_t s_s8[28*65];

    int r = lane / 14;
    int q = lane - r*14;
    bool active = (lane < 28);
    int rr = active ? r : 0;
    int row = 2*i + rr;
    int col = tile*14 + q;

    const float* xp = x + (((size_t)b*C + wid*32)*H + row)*H + col;

    uint32_t pk = 0;
    #pragma unroll
    for (int k = 0; k < 32; k++) {
        float v = active ? xp[(size_t)k*H*H] : 0.f;
        int s = (v > 0.f) - (v < 0.f);
        pk |= ((uint32_t)(uint8_t)(int8_t)s) << ((k & 3)*8);
        if ((k & 3) == 3) {
            if (active) s_s8[lane*65 + wid*8 + (k >> 2)] = pk;
            pk = 0;
        }
        float rs = v  + __shfl_down_sync(0xffffffffu, v, 14);
        float ps = rs + __shfl_down_sync(0xffffffffu, rs, 1);
        if (lane < 14 && (lane & 1) == 0)
            s_pool[(lane >> 1)*256 + wid*32 + k] = ps * 0.25f;
    }
    __syncthreads();

    for (int idx = tid; idx < 28*64; idx += 256) {
        int p = idx >> 6, c4 = idx & 63;
        int pr = p / 14, pq = p - pr*14;
        size_t rb = (((size_t)b*HP + (2*i + pr + 1))*HP + (tile*14 + pq + 1))*64;
        g_x8u[rb + c4] = s_s8[p*65 + c4];
    }
    for (int idx = tid; idx < 7*256; idx += 256) {
        int jl = idx >> 8, c = idx & 255;
        g_pool[ (((size_t)b*OH + i)*OH + tile*7 + jl)*C + c ] = s_pool[idx];
    }
}

// ---------------- IMMA conv3x3 + BN + pool + XNOR 1x1 + BN + concat ----------------
// Block = 64 output pixels x 256 co, 256 threads (8 warps, warp = 32co x 64pix).
#define WSTRIDE 80
#define XSTRIDE 80
#define WBUF_SZ (256*WSTRIDE)          // 20480
#define XBUF_SZ (64*XSTRIDE)           // 5120
#define BUF_SZ  (WBUF_SZ + XBUF_SZ)    // 25600
#define OFF_SH   67584                 // after s_dots 256*66*4
#define OFF_SHB  133376                // after s_h 64*257*4
#define SMEM_BYTES 135680

__global__ void __launch_bounds__(256) conv_mma(
    const float* __restrict__ g3, const float* __restrict__ b3,
    const float* __restrict__ m3, const float* __restrict__ v3,
    const float* __restrict__ g1, const float* __restrict__ b1,
    const float* __restrict__ m1, const float* __restrict__ v1,
    float* __restrict__ out)
{
    extern __shared__ __align__(16) char smem[];
    int tid = threadIdx.x, wid = tid >> 5, lane = tid & 31;
    int g = lane >> 2, tg = lane & 3;
    int p0 = blockIdx.x * 64;

    // staging geometry: thread t stages pixel t>>2, 16B-chunk t&3
    int pixs = p0 + (tid >> 2);
    int zi = tid & 3;
    int bbs = pixs / 784;
    int rms = pixs - bbs*784;
    int iis = rms / 28;
    int jjs = rms - iis*28;
    const char* xrow = (const char*)g_x8u + ((((size_t)bbs*HP + 2*iis)*HP + 2*jjs) << 8);
    int cobase = tid >> 2;

    int acc[2][8][4];
    #pragma unroll
    for (int m = 0; m < 2; m++)
        #pragma unroll
        for (int n = 0; n < 8; n++)
            #pragma unroll
            for (int k = 0; k < 4; k++) acc[m][n][k] = 0;

    uint4 wst[4]; uint4 xst;
    #define LDG_STAGE(s) do { \
        int tap_ = (s) >> 2, chunk_ = (s) & 3; \
        int kh_ = (tap_*11) >> 5; int kw_ = tap_ - kh_*3; \
        xst = *(const uint4*)(xrow + (kh_*HP + kw_)*256 + chunk_*64 + zi*16); \
        const uint4* wsrc_ = (const uint4*)g_w3q + (size_t)(tap_*4 + chunk_)*1024; \
        _Pragma("unroll") \
        for (int r_ = 0; r_ < 4; r_++) \
            wst[r_] = wsrc_[(cobase + 64*r_)*4 + zi]; \
    } while (0)
    #define STS_STAGE(bf) do { \
        char* base_ = smem + (bf)*BUF_SZ; \
        _Pragma("unroll") \
        for (int r_ = 0; r_ < 4; r_++) \
            *(uint4*)(base_ + (cobase + 64*r_)*WSTRIDE + zi*16) = wst[r_]; \
        *(uint4*)(base_ + WBUF_SZ + cobase*XSTRIDE + zi*16) = xst; \
    } while (0)

    LDG_STAGE(0); STS_STAGE(0);
    LDG_STAGE(1);

    int m0 = wid*32;
    for (int s = 0; s < 36; s++) {
        __syncthreads();
        if (s + 1 < 36) STS_STAGE((s+1) & 1);
        if (s + 2 < 36) LDG_STAGE(s+2);

        const char* Wb = smem + (s & 1)*BUF_SZ;
        const char* Xb = Wb + WBUF_SZ;
        #pragma unroll
        for (int ks = 0; ks < 2; ks++) {
            uint32_t a[2][4], b[8][2];
            #pragma unroll
            for (int m = 0; m < 2; m++) {
                const char* pa = Wb + (m0 + m*16 + g)*WSTRIDE + ks*32 + tg*4;
                a[m][0] = *(const uint32_t*)pa;
                a[m][1] = *(const uint32_t*)(pa + 8*WSTRIDE);
                a[m][2] = *(const uint32_t*)(pa + 16);
                a[m][3] = *(const uint32_t*)(pa + 8*WSTRIDE + 16);
            }
            #pragma unroll
            for (int n = 0; n < 8; n++) {
                const char* pb = Xb + (n*8 + g)*XSTRIDE + ks*32 + tg*4;
                b[n][0] = *(const uint32_t*)pb;
                b[n][1] = *(const uint32_t*)(pb + 16);
            }
            #pragma unroll
            for (int m = 0; m < 2; m++)
                #pragma unroll
                for (int n = 0; n < 8; n++)
                    mma_s8(acc[m][n], a[m], b[n]);
        }
    }
    __syncthreads();   // buffers dead; epilogue region reusable

    // ---- frag dump: acc -> s_dots[co][66] ----
    uint32_t* s_dots = (uint32_t*)smem;
    #pragma unroll
    for (int m = 0; m < 2; m++) {
        int co = m0 + m*16 + g;
        #pragma unroll
        for (int n = 0; n < 8; n++) {
            int px = n*8 + tg*2;
            *(uint2*)&s_dots[co*66 + px]     = make_uint2((uint32_t)acc[m][n][0], (uint32_t)acc[m][n][1]);
            *(uint2*)&s_dots[(co+8)*66 + px] = make_uint2((uint32_t)acc[m][n][2], (uint32_t)acc[m][n][3]);
        }
    }
    __syncthreads();

    // ---- pass2: BN3 + pool shortcut, build h + sign bits ----
    float* s_h = (float*)(smem + OFF_SH);
    uint32_t* s_hb = (uint32_t*)(smem + OFF_SHB);
    {
        int co = tid;
        float inv = g3[co] * rsqrtf(v3[co] + EPSV);
        float add = b3[co] - m3[co]*inv;
        #pragma unroll 4
        for (int px = 0; px < 64; px++) {
            int dot = (int)s_dots[co*66 + px];
            float hv = (float)dot*inv + add + g_pool[(size_t)(p0 + px)*C + co];
            s_h[px*257 + co] = hv;
            uint32_t mk = __ballot_sync(0xffffffffu, hv > 0.f);
            if (lane == 0) s_hb[px*9 + wid] = mk;
        }
    }
    __syncthreads();

    // ---- phase C: XNOR 1x1 + BN + concat(h,h) ----
    uint32_t hb[2][8];
    #pragma unroll
    for (int pg = 0; pg < 2; pg++)
        #pragma unroll
        for (int w = 0; w < 8; w++)
            hb[pg][w] = s_hb[(pg*32 + lane)*9 + w];

    size_t ob[2];
    #pragma unroll
    for (int pg = 0; pg < 2; pg++) {
        int p = p0 + pg*32 + lane;
        int b2 = p / 784;
        int rm2 = p - b2*784;
        ob[pg] = (size_t)b2*512*784 + rm2;
    }

    const uint4* wtab = (const uint4*)g_w1bits;
    for (int co2 = wid; co2 < 512; co2 += 8) {
        uint4 w0  = __ldg(wtab + co2*2);
        uint4 w1q = __ldg(wtab + co2*2 + 1);
        float i1 = __ldg(g1 + co2) * rsqrtf(__ldg(v1 + co2) + EPSV);
        float a1 = __ldg(b1 + co2) - __ldg(m1 + co2)*i1;
        int hc = co2 & 255;
        #pragma unroll
        for (int pg = 0; pg < 2; pg++) {
            int P = 0;
            P += __popc(hb[pg][0] ^ w0.x);  P += __popc(hb[pg][1] ^ w0.y);
            P += __popc(hb[pg][2] ^ w0.z);  P += __popc(hb[pg][3] ^ w0.w);
            P += __popc(hb[pg][4] ^ w1q.x); P += __popc(hb[pg][5] ^ w1q.y);
            P += __popc(hb[pg][6] ^ w1q.z); P += __popc(hb[pg][7] ^ w1q.w);
            float hv = s_h[(pg*32 + lane)*257 + hc];
            out[ob[pg] + (size_t)co2*784] = (float)(256 - 2*P)*i1 + a1 + hv;
        }
    }
}

// ---------------- launch ----------------
extern "C" void kernel_launch(void* const* d_in, const int* in_sizes, int n_in,
                              void* d_out, int out_size) {
    const float* x  = (const float*)d_in[0];
    const float* w3 = (const float*)d_in[1];
    const float* g3 = (const float*)d_in[2];
    const float* b3 = (const float*)d_in[3];
    const float* m3 = (const float*)d_in[4];
    const float* v3 = (const float*)d_in[5];
    const float* w1 = (const float*)d_in[6];
    const float* g1 = (const float*)d_in[7];
    const float* b1 = (const float*)d_in[8];
    const float* m1 = (const float*)d_in[9];
    const float* v1 = (const float*)d_in[10];
    float* out = (float*)d_out;

    cudaFuncSetAttribute(conv_mma, cudaFuncAttributeMaxDynamicSharedMemorySize, SMEM_BYTES);

    pack_w<<<(9*4*256*16 + 2*C*8 + 255)/256, 256>>>(w3, w1);
    border_zero<<<BB, 256>>>();
    packx8_pool<<<dim3(4, OH, BB), 256>>>(x);
    conv_mma<<<NBLK, 256, SMEM_BYTES>>>(g3, b3, m3, v3, g1, b1, m1, v1, out);
}

// round 9
// speedup vs baseline: 1.9743x; 1.3084x over previous
#include <cuda_runtime.h>
#include <stdint.h>

#define BB 32
#define C  256
#define H  56
#define OH 28
#define HP 58
#define EPSV 1e-5f
#define NPIX (BB*OH*OH)     // 25088
#define NBLK (NPIX/64)      // 392

// ---------------- scratch ----------------
__device__ uint32_t g_x8u[BB*HP*HP*64];       // s8 sign(x), padded, channel-last
__device__ uint32_t g_w3f[72*16*32*4];        // frag-major W: [k32][mt16][lane32][4 u32]
__device__ uint32_t g_w1bits[2*C*8];          // 1x1 weight sign bits
__device__ float    g_pool[(size_t)NPIX*C];   // [pix][c]

// ---------------- s8 mma ----------------
__device__ __forceinline__ void mma_s8(int* c, const uint32_t* a, const uint32_t* b) {
    asm volatile(
        "mma.sync.aligned.m16n8k32.row.col.s32.s8.s8.s32 "
        "{%0,%1,%2,%3}, {%4,%5,%6,%7}, {%8,%9}, {%0,%1,%2,%3};"
        : "+r"(c[0]), "+r"(c[1]), "+r"(c[2]), "+r"(c[3])
        : "r"(a[0]), "r"(a[1]), "r"(a[2]), "r"(a[3]), "r"(b[0]), "r"(b[1]));
}
__device__ __forceinline__ void cpa16(uint32_t d, const void* s) {
    asm volatile("cp.async.cg.shared.global [%0], [%1], 16;" :: "r"(d), "l"(s));
}
#define CP_COMMIT() asm volatile("cp.async.commit_group;" ::: "memory")
#define CP_WAIT1()  asm volatile("cp.async.wait_group 1;" ::: "memory")
__device__ __forceinline__ uint32_t smem_u32(const void* p) {
    uint32_t a;
    asm("{ .reg .u64 t; cvta.to.shared.u64 t, %1; cvt.u32.u64 %0, t; }" : "=r"(a) : "l"(p));
    return a;
}

// ---------------- weight packing (frag-major W3 + bit-packed W1) ----------------
__global__ void pack_w(const float* __restrict__ w3, const float* __restrict__ w1) {
    int t = blockIdx.x*256 + threadIdx.x;
    if (t < 72*16*32*4) {
        int k32  = t >> 11;
        int rem  = t & 2047;
        int mt   = rem >> 7;
        int rem2 = rem & 127;
        int lane = rem2 >> 2;
        int r    = rem2 & 3;
        int g = lane >> 2, tg = lane & 3;
        int co  = mt*16 + g + (r & 1)*8;
        int tap = k32 >> 3, chq = k32 & 7;
        int chb = chq*32 + ((r >> 1) << 4) + tg*4;
        uint32_t pk = 0;
        #pragma unroll
        for (int z = 0; z < 4; z++) {
            float v = w3[((size_t)co*256 + chb + z)*9 + tap];
            int s = (v > 0.f) - (v < 0.f);
            pk |= ((uint32_t)(uint8_t)(int8_t)s) << (z*8);
        }
        g_w3f[t] = pk;
    } else if (t < 72*16*32*4 + 2*C*8) {
        int tt = t - 72*16*32*4;
        int co = tt >> 3, word = tt & 7;
        const float* p = w1 + (size_t)co*C + word*32;
        uint32_t bits = 0;
        #pragma unroll
        for (int j = 0; j < 32; j++)
            if (p[j] > 0.f) bits |= (1u << j);
        g_w1bits[tt] = bits;
    }
}

// ---------------- zero padded border of X8 ----------------
__global__ void border_zero() {
    int b = blockIdx.x, t = threadIdx.x;
    size_t base = (size_t)b*HP*HP*64;
    for (int i = t; i < HP*64; i += 256) {
        g_x8u[base + i] = 0;
        g_x8u[base + (size_t)(HP-1)*HP*64 + i] = 0;
    }
    for (int i = t; i < (HP-2)*64; i += 256) {
        int r = i >> 6, c = i & 63;
        g_x8u[base + (size_t)(r+1)*HP*64 + c] = 0;
        g_x8u[base + (size_t)(r+1)*HP*64 + (HP-1)*64 + c] = 0;
    }
}

// ---------------- fused s8-pack(sign(x)) + avgpool2x2 ----------------
__global__ void __launch_bounds__(256) packx8_pool(const float* __restrict__ x) {
    int tile = blockIdx.x;
    int i    = blockIdx.y;
    int b    = blockIdx.z;
    int tid = threadIdx.x, wid = tid >> 5, lane = tid & 31;

    __shared__ float    s_pool[7*256];
    __shared__ uint32_t s_s8[28*65];

    int r = lane / 14;
    int q = lane - r*14;
    bool active = (lane < 28);
    int rr = active ? r : 0;
    int row = 2*i + rr;
    int col = tile*14 + q;

    const float* xp = x + (((size_t)b*C + wid*32)*H + row)*H + col;

    uint32_t pk = 0;
    #pragma unroll
    for (int k = 0; k < 32; k++) {
        float v = active ? xp[(size_t)k*H*H] : 0.f;
        int s = (v > 0.f) - (v < 0.f);
        pk |= ((uint32_t)(uint8_t)(int8_t)s) << ((k & 3)*8);
        if ((k & 3) == 3) {
            if (active) s_s8[lane*65 + wid*8 + (k >> 2)] = pk;
            pk = 0;
        }
        float rs = v  + __shfl_down_sync(0xffffffffu, v, 14);
        float ps = rs + __shfl_down_sync(0xffffffffu, rs, 1);
        if (lane < 14 && (lane & 1) == 0)
            s_pool[(lane >> 1)*256 + wid*32 + k] = ps * 0.25f;
    }
    __syncthreads();

    for (int idx = tid; idx < 28*64; idx += 256) {
        int p = idx >> 6, c4 = idx & 63;
        int pr = p / 14, pq = p - pr*14;
        size_t rb = (((size_t)b*HP + (2*i + pr + 1))*HP + (tile*14 + pq + 1))*64;
        g_x8u[rb + c4] = s_s8[p*65 + c4];
    }
    for (int idx = tid; idx < 7*256; idx += 256) {
        int jl = idx >> 8, c = idx & 255;
        g_pool[ (((size_t)b*OH + i)*OH + tile*7 + jl)*C + c ] = s_pool[idx];
    }
}

// ---------------- IMMA conv3x3 + BN + pool + XNOR 1x1 + BN + concat ----------------
// Block = 64 pixels x 256 co, 256 threads. cp.async 3-deep pipeline,
// frag-major W (LDS.128 A-frags). Epilogue in-place in the dots region.
#define WBUF_SZ 16384                   // 2 k32-steps x [mt16][lane32][16B]
#define XBUF_SZ (64*80)                 // 64 pix rows, 80B stride (64B data)
#define BUF_SZ  (WBUF_SZ + XBUF_SZ)     // 21504
#define OFF_SHB (256*66*4)              // 67584 (dots/h region)
#define SMEM_BYTES (OFF_SHB + 64*9*4)   // 69888

__global__ void __launch_bounds__(256, 2) conv_mma(
    const float* __restrict__ g3, const float* __restrict__ b3,
    const float* __restrict__ m3, const float* __restrict__ v3,
    const float* __restrict__ g1, const float* __restrict__ b1,
    const float* __restrict__ m1, const float* __restrict__ v1,
    float* __restrict__ out)
{
    extern __shared__ __align__(16) char smem[];
    uint32_t sb = smem_u32(smem);
    int tid = threadIdx.x, wid = tid >> 5, lane = tid & 31;
    int g = lane >> 2, tg = lane & 3;
    int p0 = blockIdx.x * 64;

    // staging geometry: thread t stages pixel t>>2, 16B-quarter t&3
    int pixrel = tid >> 2;
    int zi = tid & 3;
    int pixs = p0 + pixrel;
    int bbs = pixs / 784;
    int rms = pixs - bbs*784;
    int iis = rms / 28;
    int jjs = rms - iis*28;
    const char* xrow = (const char*)g_x8u + ((((size_t)bbs*HP + 2*iis)*HP + 2*jjs) << 8);

    int acc[2][8][4];
    #pragma unroll
    for (int m = 0; m < 2; m++)
        #pragma unroll
        for (int n = 0; n < 8; n++)
            #pragma unroll
            for (int k = 0; k < 4; k++) acc[m][n][k] = 0;

    #define ISSUE(s) do { \
        int tap_ = (s) >> 2, chunk_ = (s) & 3; \
        int kh_ = tap_ / 3, kw_ = tap_ - kh_*3; \
        uint32_t bd = sb + ((s) % 3)*BUF_SZ; \
        const char* ws_ = (const char*)g_w3f + (size_t)(s)*16384; \
        cpa16(bd + (uint32_t)tid*16,         ws_ + (size_t)tid*16); \
        cpa16(bd + (uint32_t)(tid+256)*16,   ws_ + (size_t)(tid+256)*16); \
        cpa16(bd + (uint32_t)(tid+512)*16,   ws_ + (size_t)(tid+512)*16); \
        cpa16(bd + (uint32_t)(tid+768)*16,   ws_ + (size_t)(tid+768)*16); \
        cpa16(bd + WBUF_SZ + (uint32_t)pixrel*80 + zi*16, \
              xrow + (kh_*HP + kw_)*256 + chunk_*64 + zi*16); \
    } while (0)

    ISSUE(0); CP_COMMIT();
    ISSUE(1); CP_COMMIT();

    for (int s = 0; s < 36; s++) {
        CP_WAIT1();
        __syncthreads();
        if (s + 2 < 36) ISSUE(s + 2);
        CP_COMMIT();

        const char* Bf = smem + (s % 3)*BUF_SZ;
        #pragma unroll
        for (int ks = 0; ks < 2; ks++) {
            uint32_t a[2][4], b[8][2];
            #pragma unroll
            for (int m = 0; m < 2; m++) {
                uint4 av = *(const uint4*)(Bf + ks*8192 + (wid*2 + m)*512 + lane*16);
                a[m][0] = av.x; a[m][1] = av.y; a[m][2] = av.z; a[m][3] = av.w;
            }
            const char* Xb = Bf + WBUF_SZ;
            #pragma unroll
            for (int n = 0; n < 8; n++) {
                const char* pb = Xb + (n*8 + g)*80 + ks*32 + tg*4;
                b[n][0] = *(const uint32_t*)pb;
                b[n][1] = *(const uint32_t*)(pb + 16);
            }
            #pragma unroll
            for (int m = 0; m < 2; m++)
                #pragma unroll
                for (int n = 0; n < 8; n++)
                    mma_s8(acc[m][n], a[m], b[n]);
        }
    }
    __syncthreads();   // buffers dead; dots region reusable

    // ---- frag dump: acc -> s_dots[co][66] ----
    uint32_t* s_dots = (uint32_t*)smem;
    int m0 = wid*32;
    #pragma unroll
    for (int m = 0; m < 2; m++) {
        int co = m0 + m*16 + g;
        #pragma unroll
        for (int n = 0; n < 8; n++) {
            int px = n*8 + tg*2;
            *(uint2*)&s_dots[co*66 + px]     = make_uint2((uint32_t)acc[m][n][0], (uint32_t)acc[m][n][1]);
            *(uint2*)&s_dots[(co+8)*66 + px] = make_uint2((uint32_t)acc[m][n][2], (uint32_t)acc[m][n][3]);
        }
    }
    __syncthreads();

    // ---- pass2: BN3 + pool shortcut, h written IN PLACE; sign bits ----
    float* s_hf = (float*)smem;
    uint32_t* s_hb = (uint32_t*)(smem + OFF_SHB);
    {
        int co = tid;
        float inv = g3[co] * rsqrtf(v3[co] + EPSV);
        float add = b3[co] - m3[co]*inv;
        #pragma unroll 4
        for (int px = 0; px < 64; px++) {
            int dot = (int)s_dots[co*66 + px];
            float hv = (float)dot*inv + add + g_pool[(size_t)(p0 + px)*C + co];
            s_hf[co*66 + px] = hv;
            uint32_t mk = __ballot_sync(0xffffffffu, hv > 0.f);
            if (lane == 0) s_hb[px*9 + wid] = mk;
        }
    }
    __syncthreads();

    // ---- phase C: XNOR 1x1 + BN + concat(h,h) ----
    uint32_t hb[2][8];
    #pragma unroll
    for (int pg = 0; pg < 2; pg++)
        #pragma unroll
        for (int w = 0; w < 8; w++)
            hb[pg][w] = s_hb[(pg*32 + lane)*9 + w];

    size_t ob[2];
    #pragma unroll
    for (int pg = 0; pg < 2; pg++) {
        int p = p0 + pg*32 + lane;
        int b2 = p / 784;
        int rm2 = p - b2*784;
        ob[pg] = (size_t)b2*512*784 + rm2;
    }

    const uint4* wtab = (const uint4*)g_w1bits;
    for (int co2 = wid; co2 < 512; co2 += 8) {
        uint4 w0  = __ldg(wtab + co2*2);
        uint4 w1q = __ldg(wtab + co2*2 + 1);
        float i1 = __ldg(g1 + co2) * rsqrtf(__ldg(v1 + co2) + EPSV);
        float a1 = __ldg(b1 + co2) - __ldg(m1 + co2)*i1;
        int hc = co2 & 255;
        #pragma unroll
        for (int pg = 0; pg < 2; pg++) {
            int P = 0;
            P += __popc(hb[pg][0] ^ w0.x);  P += __popc(hb[pg][1] ^ w0.y);
            P += __popc(hb[pg][2] ^ w0.z);  P += __popc(hb[pg][3] ^ w0.w);
            P += __popc(hb[pg][4] ^ w1q.x); P += __popc(hb[pg][5] ^ w1q.y);
            P += __popc(hb[pg][6] ^ w1q.z); P += __popc(hb[pg][7] ^ w1q.w);
            float hv = s_hf[hc*66 + pg*32 + lane];
            out[ob[pg] + (size_t)co2*784] = (float)(256 - 2*P)*i1 + a1 + hv;
        }
    }
}

// ---------------- launch ----------------
extern "C" void kernel_launch(void* const* d_in, const int* in_sizes, int n_in,
                              void* d_out, int out_size) {
    const float* x  = (const float*)d_in[0];
    const float* w3 = (const float*)d_in[1];
    const float* g3 = (const float*)d_in[2];
    const float* b3 = (const float*)d_in[3];
    const float* m3 = (const float*)d_in[4];
    const float* v3 = (const float*)d_in[5];
    const float* w1 = (const float*)d_in[6];
    const float* g1 = (const float*)d_in[7];
    const float* b1 = (const float*)d_in[8];
    const float* m1 = (const float*)d_in[9];
    const float* v1 = (const float*)d_in[10];
    float* out = (float*)d_out;

    cudaFuncSetAttribute(conv_mma, cudaFuncAttributeMaxDynamicSharedMemorySize, SMEM_BYTES);

    pack_w<<<(72*16*32*4 + 2*C*8 + 255)/256, 256>>>(w3, w1);
    border_zero<<<BB, 256>>>();
    packx8_pool<<<dim3(4, OH, BB), 256>>>(x);
    conv_mma<<<NBLK, 256, SMEM_BYTES>>>(g3, b3, m3, v3, g1, b1, m1, v1, out);
}